// round 10
// baseline (speedup 1.0000x reference)
#include <cuda_runtime.h>
#include <cstdint>

// Problem constants (fixed by reference setup_inputs)
#define C_CLS 256
#define S_SUP 5
#define Q_QRY 64
#define DIN   1024
#define ZD    128
#define CS    (C_CLS*S_SUP)              // 1280
#define CQ    (C_CLS*Q_QRY)              // 16384
#define M_TOT (CS+CQ)                    // 17664
#define NPAIRS (C_CLS*(Q_QRY*(Q_QRY-1)/2)) // 516096
#define EPSF  1e-8f
#define NSTG  64                          // k_gemm: K stages of 16
#define DLSTG 8                           // k_dloo: K stages of 16

// k_gemm smem geometry (floats)
#define GA_H   1040                       // per-kc (8-k) A stride, bank-padded
#define GA_ALL 2080                       // Ah region size (2 kc)
#define G_BH   4160                       // Bh base
#define G_BL   6208                       // Bl base
#define G_BUF  8256                       // per-buffer floats (33 KB)
// k_dloo smem geometry
#define D_BH   4160
#define D_BL   8256
#define D_BUF  12352                      // per-buffer floats (49.4 KB)

// ---------------- device scratch (no allocations allowed) ----------------
__device__ __align__(16) float g_z[(size_t)M_TOT * ZD];        // ~9 MB
__device__ __align__(16) float g_proto2[C_CLS];                // ||proto_c||^2
__device__ __align__(16) float g_row2[M_TOT];                  // ||z_row||^2
// W tf32 hi/lo images: [k8_idx(128)][n(128)][8 pos-permuted]
__device__ __align__(16) float g_Wh[128 * 1024];               // 512 KB
__device__ __align__(16) float g_Wl[128 * 1024];               // 512 KB
// protoT tf32 hi/lo images: [k8(16)][n(256)][8 pos]
__device__ __align__(16) float g_Ph[16 * 2048];                // 128 KB
__device__ __align__(16) float g_Pl[16 * 2048];                // 128 KB
__device__ float g_cos_sum;
__device__ float g_acc_cnt;

// ---------------- helpers ----------------
__device__ __forceinline__ uint32_t smem_u32(const void* p){
    uint32_t a; asm("{ .reg .u64 t; cvta.to.shared.u64 t, %1; cvt.u32.u64 %0, t; }"
                    : "=r"(a) : "l"(p));
    return a;
}
__device__ __forceinline__ float tf32_rna(float a){
    uint32_t r; asm("cvt.rna.tf32.f32 %0, %1;" : "=r"(r) : "f"(a));
    return __uint_as_float(r);
}
__device__ __forceinline__ void cp16(uint32_t saddr, const void* g){
    asm volatile("cp.async.cg.shared.global [%0], [%1], 16;" :: "r"(saddr), "l"(g));
}
#define CP_COMMIT() asm volatile("cp.async.commit_group;" ::: "memory")
#define CP_WAIT0()  asm volatile("cp.async.wait_group 0;"  ::: "memory")

// D += A(16x8,row) * B(8x8,col)   tf32 inputs, fp32 accum (validated R5-R9)
__device__ __forceinline__ void mma8(float4 &d, float2 a01, float2 a23, float2 b){
    asm volatile("mma.sync.aligned.m16n8k8.row.col.f32.tf32.tf32.f32 "
        "{%0,%1,%2,%3}, {%4,%5,%6,%7}, {%8,%9}, {%0,%1,%2,%3};"
        : "+f"(d.x), "+f"(d.y), "+f"(d.z), "+f"(d.w)
        : "r"(__float_as_uint(a01.x)), "r"(__float_as_uint(a23.x)),
          "r"(__float_as_uint(a01.y)), "r"(__float_as_uint(a23.y)),
          "r"(__float_as_uint(b.x)),   "r"(__float_as_uint(b.y)));
}
// split raw float4 into tf32 hi + residual lo (at staging time)
__device__ __forceinline__ void split4(float4 v, float4 &hi, float4 &lo){
    hi.x = tf32_rna(v.x); hi.y = tf32_rna(v.y);
    hi.z = tf32_rna(v.z); hi.w = tf32_rna(v.w);
    lo.x = v.x - hi.x; lo.y = v.y - hi.y;
    lo.z = v.z - hi.z; lo.w = v.w - hi.w;
}

// =====================================================================
// KW: split W[k=1024][n=128] into tf32 hi/lo pos-order images
// [k0,k4,k1,k5,k2,k6,k3,k7] per k8-chunk row (validated R6 layout).
// =====================================================================
__global__ __launch_bounds__(256) void k_wsplit(const float* __restrict__ W){
    const int s   = blockIdx.x;          // 0..31 (4 k8-chunks each)
    const int t   = threadIdx.x;
    const int n   = t >> 1;
    const int h   = t & 1;
#pragma unroll
    for (int kc = 0; kc < 4; kc++){
        const int kb = s * 32 + kc * 8 + 2 * h;
        const float v0 = W[(size_t)(kb + 0) * ZD + n];
        const float v1 = W[(size_t)(kb + 1) * ZD + n];
        const float v4 = W[(size_t)(kb + 4) * ZD + n];
        const float v5 = W[(size_t)(kb + 5) * ZD + n];
        const float h0 = tf32_rna(v0), h1 = tf32_rna(v1);
        const float h4 = tf32_rna(v4), h5 = tf32_rna(v5);
        const int off = (s * 4 + kc) * 1024 + n * 8 + h * 4;
        *(float4*)&g_Wh[off] = make_float4(h0, h4, h1, h5);
        *(float4*)&g_Wl[off] = make_float4(v0 - h0, v4 - h4, v1 - h1, v5 - h5);
    }
}

// =====================================================================
// K1: z = [xs; xq] @ W, mma.sync tf32 3-pass. Hi/lo SPLIT AT STAGING:
// smem holds Ah|Al|Bh|Bl; fragments feed HMMA straight from LDS (no
// per-warp split ALU, no redundant splits). 512 threads = 16 warps
// (4m x 4n), warp tile 32x32, BK=16, 64 stages double-buffered.
// B hi/lo via cp.async from precomputed images. Epilogue: z + ||row||^2.
// =====================================================================
__global__ __launch_bounds__(512) void k_gemm(const float* __restrict__ xs,
                                              const float* __restrict__ xq){
    extern __shared__ float sb[];        // 2 x G_BUF floats (66 KB)
    __shared__ float s_r2[128];

    const int tid  = threadIdx.x;
    const int lane = tid & 31;
    const int wid  = tid >> 5;
    const int g    = lane >> 2;
    const int tg   = lane & 3;
    const int m0   = (wid & 3) * 32;
    const int n0   = (wid >> 2) * 32;
    const int bm   = blockIdx.x;
    const float* X = (bm < 10) ? (xs + (size_t)bm * (128 * DIN))
                               : (xq + (size_t)(bm - 10) * (128 * DIN));
    const int sm_m = tid >> 2;
    const int skc  = (tid >> 1) & 1;
    const int sh   = tid & 1;
    const int sts_off = skc * GA_H + sm_m * 8 + sh * 4;   // conflict-free (R8-verified)

    float4 acc[2][4];
#pragma unroll
    for (int i = 0; i < 2; i++)
#pragma unroll
        for (int j = 0; j < 4; j++) acc[i][j] = make_float4(0.f, 0.f, 0.f, 0.f);

    float4 rA;
    // prologue: stage 0
    {
        float* buf = sb;
        cp16(smem_u32(&buf[G_BH]) + tid * 16, g_Wh + tid * 4);
        cp16(smem_u32(&buf[G_BL]) + tid * 16, g_Wl + tid * 4);
        CP_COMMIT();
        const float* xp = X + (size_t)sm_m * DIN + skc * 8 + sh * 2;
        const float2 fa = *(const float2*)xp;
        const float2 fb = *(const float2*)(xp + 4);
        rA = make_float4(fa.x, fb.x, fa.y, fb.y);
        float4 hi4, lo4; split4(rA, hi4, lo4);
        *(float4*)&buf[sts_off]          = hi4;
        *(float4*)&buf[GA_ALL + sts_off] = lo4;
        CP_WAIT0();
    }
    __syncthreads();

    for (int s = 0; s < NSTG; s++){
        const int b = s & 1;
        const float* buf = sb + b * G_BUF;
        float* nbuf = sb + (b ^ 1) * G_BUF;
        if (s + 1 < NSTG){
            cp16(smem_u32(&nbuf[G_BH]) + tid * 16, g_Wh + (s + 1) * 2048 + tid * 4);
            cp16(smem_u32(&nbuf[G_BL]) + tid * 16, g_Wl + (s + 1) * 2048 + tid * 4);
            CP_COMMIT();
            const float* xp = X + (size_t)sm_m * DIN + (s + 1) * 16 + skc * 8 + sh * 2;
            const float2 fa = *(const float2*)xp;
            const float2 fb = *(const float2*)(xp + 4);
            rA = make_float4(fa.x, fb.x, fa.y, fb.y);
        }
#pragma unroll
        for (int kc = 0; kc < 2; kc++){
            const float* Ah = buf + kc * GA_H;
            const float* Al = Ah + GA_ALL;
            const float* Bh = buf + G_BH + kc * 1024;
            const float* Bl = buf + G_BL + kc * 1024;
            float2 bh[4], bl[4];
#pragma unroll
            for (int j = 0; j < 4; j++){
                const int nr = (n0 + j * 8 + g) * 8 + 2 * tg;
                bh[j] = *(const float2*)&Bh[nr];
                bl[j] = *(const float2*)&Bl[nr];
            }
#pragma unroll
            for (int mt = 0; mt < 2; mt++){
                const int r0 = (m0 + mt * 16 + g) * 8 + 2 * tg;
                const float2 ah01 = *(const float2*)&Ah[r0];
                const float2 ah23 = *(const float2*)&Ah[r0 + 64];
                const float2 al01 = *(const float2*)&Al[r0];
                const float2 al23 = *(const float2*)&Al[r0 + 64];
#pragma unroll
                for (int j = 0; j < 4; j++){
                    mma8(acc[mt][j], ah01, ah23, bh[j]);
                    mma8(acc[mt][j], al01, al23, bh[j]);
                    mma8(acc[mt][j], ah01, ah23, bl[j]);
                }
            }
        }
        if (s + 1 < NSTG){
            float4 hi4, lo4; split4(rA, hi4, lo4);
            *(float4*)&nbuf[sts_off]          = hi4;
            *(float4*)&nbuf[GA_ALL + sts_off] = lo4;
            CP_WAIT0();
            __syncthreads();
        }
    }

    // ---- epilogue: z store + fused row norms ----
    if (tid < 128) s_r2[tid] = 0.0f;
    __syncthreads();
    const size_t rb = (size_t)bm * 128;
#pragma unroll
    for (int mt = 0; mt < 2; mt++){
        const int r0 = m0 + mt * 16 + g;
        float s0 = 0.0f, s1 = 0.0f;
#pragma unroll
        for (int j = 0; j < 4; j++){
            const float4 a = acc[mt][j];
            const int col = n0 + j * 8 + 2 * tg;
            *(float2*)(g_z + (rb + r0) * ZD + col)     = make_float2(a.x, a.y);
            *(float2*)(g_z + (rb + r0 + 8) * ZD + col) = make_float2(a.z, a.w);
            s0 = fmaf(a.x, a.x, s0); s0 = fmaf(a.y, a.y, s0);
            s1 = fmaf(a.z, a.z, s1); s1 = fmaf(a.w, a.w, s1);
        }
        s0 += __shfl_xor_sync(0xffffffffu, s0, 1);
        s0 += __shfl_xor_sync(0xffffffffu, s0, 2);
        s1 += __shfl_xor_sync(0xffffffffu, s1, 1);
        s1 += __shfl_xor_sync(0xffffffffu, s1, 2);
        if (tg == 0){
            atomicAdd(&s_r2[r0],     s0);
            atomicAdd(&s_r2[r0 + 8], s1);
        }
    }
    __syncthreads();
    if (tid < 128) g_row2[rb + tid] = s_r2[tid];
}

// ---------------- K2: prototypes + ||proto||^2 + hi/lo images ------------
// Image layout [k8(16)][n(256)][8 pos]. Also zeroes global accumulators.
__global__ __launch_bounds__(128) void k_proto(){
    const int c = blockIdx.x;
    const int d = threadIdx.x;  // 0..127 (= k index)
    if (c == 0 && d == 0){ g_cos_sum = 0.0f; g_acc_cnt = 0.0f; }
    const float* z = g_z + (size_t)c * S_SUP * ZD + d;
    float p = 0.0f;
#pragma unroll
    for (int s = 0; s < S_SUP; s++) p += z[s * ZD];
    p *= (1.0f / S_SUP);
    const int k8  = d >> 3;
    const int pos = ((d & 3) << 1) | ((d >> 2) & 1);
    const float hi = tf32_rna(p);
    const int off = k8 * 2048 + c * 8 + pos;
    g_Ph[off] = hi;
    g_Pl[off] = p - hi;
    float sq = p * p;
#pragma unroll
    for (int o = 16; o; o >>= 1) sq += __shfl_xor_sync(0xffffffffu, sq, o);
    __shared__ float w[4];
    if ((d & 31) == 0) w[d >> 5] = sq;
    __syncthreads();
    if (d == 0) g_proto2[c] = w[0] + w[1] + w[2] + w[3];
}

// =====================================================================
// K3 (fused d2 + loo): one CTA per 2 classes. GEMM M=128 x N=256 x K=128,
// 3-pass tf32, hi/lo split at staging (A) / precomputed (B images).
// 16 warps: 4m x 4n, warp tile 32x64 (acc[2][8]). d2 -> SMEM (stride
// 264) then in-CTA loo-norm + cos identity + argmin for both classes.
// cos: sum_{q<k} a_q.a_k = ( ||sum_q a_q||^2 - sum_q ||a_q||^2 ) / 2
// =====================================================================
__global__ __launch_bounds__(512) void k_dloo(){
    extern __shared__ float sb[];        // max(2*D_BUF, 128*264) floats
    __shared__ float s_part[16][256];
    __shared__ float s_red[16];
    __shared__ float s_scal[4];          // [sumA2_c0, cnt_c0, sumA2_c1, cnt_c1]

    const int tid  = threadIdx.x;
    const int lane = tid & 31;
    const int wid  = tid >> 5;           // 0..15
    const int g    = lane >> 2;
    const int tg   = lane & 3;
    const int m0   = (wid & 3) * 32;
    const int n0   = (wid >> 2) * 64;
    const int qb   = blockIdx.x;         // class pair
    const float* X = g_z + (size_t)(CS + qb * 128) * ZD;
    const int sm_m = tid >> 2;
    const int skc  = (tid >> 1) & 1;
    const int sh   = tid & 1;
    const int sts_off = skc * GA_H + sm_m * 8 + sh * 4;

    if (tid < 4) s_scal[tid] = 0.0f;

    float4 acc[2][8];
#pragma unroll
    for (int i = 0; i < 2; i++)
#pragma unroll
        for (int j = 0; j < 8; j++) acc[i][j] = make_float4(0.f, 0.f, 0.f, 0.f);

    float4 rA;
    // prologue: stage 0
    {
        float* buf = sb;
        const uint32_t bh = smem_u32(&buf[D_BH]);
        const uint32_t bl = smem_u32(&buf[D_BL]);
        cp16(bh + tid * 32,      g_Ph + tid * 8);
        cp16(bh + tid * 32 + 16, g_Ph + tid * 8 + 4);
        cp16(bl + tid * 32,      g_Pl + tid * 8);
        cp16(bl + tid * 32 + 16, g_Pl + tid * 8 + 4);
        CP_COMMIT();
        const float* xp = X + (size_t)sm_m * ZD + skc * 8 + sh * 2;
        const float2 fa = *(const float2*)xp;
        const float2 fb = *(const float2*)(xp + 4);
        rA = make_float4(fa.x, fb.x, fa.y, fb.y);
        float4 hi4, lo4; split4(rA, hi4, lo4);
        *(float4*)&buf[sts_off]          = hi4;
        *(float4*)&buf[GA_ALL + sts_off] = lo4;
        CP_WAIT0();
    }
    __syncthreads();

    for (int s = 0; s < DLSTG; s++){
        const int b = s & 1;
        const float* buf = sb + b * D_BUF;
        float* nbuf = sb + (b ^ 1) * D_BUF;
        if (s + 1 < DLSTG){
            const uint32_t bh = smem_u32(&nbuf[D_BH]);
            const uint32_t bl = smem_u32(&nbuf[D_BL]);
            const float* sH = g_Ph + (s + 1) * 4096;
            const float* sL = g_Pl + (s + 1) * 4096;
            cp16(bh + tid * 32,      sH + tid * 8);
            cp16(bh + tid * 32 + 16, sH + tid * 8 + 4);
            cp16(bl + tid * 32,      sL + tid * 8);
            cp16(bl + tid * 32 + 16, sL + tid * 8 + 4);
            CP_COMMIT();
            const float* xp = X + (size_t)sm_m * ZD + (s + 1) * 16 + skc * 8 + sh * 2;
            const float2 fa = *(const float2*)xp;
            const float2 fb = *(const float2*)(xp + 4);
            rA = make_float4(fa.x, fb.x, fa.y, fb.y);
        }
#pragma unroll
        for (int kc = 0; kc < 2; kc++){
            const float* Ah = buf + kc * GA_H;
            const float* Al = Ah + GA_ALL;
            const float* Bh = buf + D_BH + kc * 2048;
            const float* Bl = buf + D_BL + kc * 2048;
#pragma unroll
            for (int mt = 0; mt < 2; mt++){
                const int r0 = (m0 + mt * 16 + g) * 8 + 2 * tg;
                const float2 ah01 = *(const float2*)&Ah[r0];
                const float2 ah23 = *(const float2*)&Ah[r0 + 64];
                const float2 al01 = *(const float2*)&Al[r0];
                const float2 al23 = *(const float2*)&Al[r0 + 64];
#pragma unroll
                for (int j = 0; j < 8; j++){
                    const int nr = (n0 + j * 8 + g) * 8 + 2 * tg;
                    const float2 bh = *(const float2*)&Bh[nr];
                    const float2 bl = *(const float2*)&Bl[nr];
                    mma8(acc[mt][j], ah01, ah23, bh);
                    mma8(acc[mt][j], al01, al23, bh);
                    mma8(acc[mt][j], ah01, ah23, bl);
                }
            }
        }
        if (s + 1 < DLSTG){
            float4 hi4, lo4; split4(rA, hi4, lo4);
            *(float4*)&nbuf[sts_off]          = hi4;
            *(float4*)&nbuf[GA_ALL + sts_off] = lo4;
            CP_WAIT0();
            __syncthreads();
        }
    }

    // ---- d2 into SMEM (reuses stage buffers; stride 264) ----
    __syncthreads();                     // all warps done reading buffers
    float* d2s = sb;                     // 128 x 264 floats
#pragma unroll
    for (int mt = 0; mt < 2; mt++){
        const int r = m0 + mt * 16 + g;
        const float qn0 = g_row2[CS + qb * 128 + r];
        const float qn1 = g_row2[CS + qb * 128 + r + 8];
#pragma unroll
        for (int j = 0; j < 8; j++){
            const int col = n0 + j * 8 + 2 * tg;
            const float pn0 = g_proto2[col];
            const float pn1 = g_proto2[col + 1];
            const float4 a = acc[mt][j];
            *(float2*)&d2s[r * 264 + col] =
                make_float2(qn0 + pn0 - 2.0f * a.x, qn0 + pn1 - 2.0f * a.y);
            *(float2*)&d2s[(r + 8) * 264 + col] =
                make_float2(qn1 + pn0 - 2.0f * a.z, qn1 + pn1 - 2.0f * a.w);
        }
    }
    __syncthreads();

    // ---- loo: warp w -> rows w*8..w*8+7; class = 2qb + (w>>3) ----
    const int cls = 2 * qb + (wid >> 3);
    const float* D = d2s + (size_t)(wid * 8) * 264 + lane * 8;
    float d2v[8][8];
#pragma unroll
    for (int r = 0; r < 8; r++){
        const float4 v0 = *(const float4*)(D + r * 264);
        const float4 v1 = *(const float4*)(D + r * 264 + 4);
        d2v[r][0] = v0.x; d2v[r][1] = v0.y; d2v[r][2] = v0.z; d2v[r][3] = v0.w;
        d2v[r][4] = v1.x; d2v[r][5] = v1.y; d2v[r][6] = v1.z; d2v[r][7] = v1.w;
    }

    float sacc[8];
#pragma unroll
    for (int j = 0; j < 8; j++) sacc[j] = 0.0f;
    float sumA2 = 0.0f;
    float cnt   = 0.0f;

#pragma unroll
    for (int r = 0; r < 8; r++){
        float ss = 0.0f;
        float mv = 3.4e38f;
        int   mi = 1 << 30;
#pragma unroll
        for (int j = 0; j < 8; j++){
            const int   p = lane * 8 + j;
            const float v = d2v[r][j];
            if (v < mv){ mv = v; mi = p; }        // ascending -> first min
            if (p != cls) ss = fmaf(v, v, ss);
        }
#pragma unroll
        for (int off = 16; off; off >>= 1){
            ss += __shfl_xor_sync(0xffffffffu, ss, off);
            const float ov = __shfl_xor_sync(0xffffffffu, mv, off);
            const int   oi = __shfl_xor_sync(0xffffffffu, mi, off);
            if (ov < mv || (ov == mv && oi < mi)){ mv = ov; mi = oi; }
        }
        const float inv = 1.0f / fmaxf(sqrtf(ss), EPSF);
#pragma unroll
        for (int j = 0; j < 8; j++){
            const int p = lane * 8 + j;
            if (p != cls) sacc[j] = fmaf(d2v[r][j], inv, sacc[j]);
        }
        if (lane == 0){
            sumA2 += ss * inv * inv;
            if (mi == cls) cnt += 1.0f;
        }
    }

#pragma unroll
    for (int j = 0; j < 8; j++) s_part[wid][lane * 8 + j] = sacc[j];
    if (lane == 0){
        atomicAdd(&s_scal[(wid >> 3) * 2],     sumA2);
        atomicAdd(&s_scal[(wid >> 3) * 2 + 1], cnt);
    }
    __syncthreads();

    // ||sum_q a_q||^2 per class: threads 0-255 -> class0, 256-511 -> class1
    {
        const int half = tid >> 8;
        const int cc   = tid & 255;
        float col = 0.0f;
#pragma unroll
        for (int w2 = 0; w2 < 8; w2++) col += s_part[half * 8 + w2][cc];
        float sq = col * col;
#pragma unroll
        for (int off = 16; off; off >>= 1) sq += __shfl_xor_sync(0xffffffffu, sq, off);
        if (lane == 0) s_red[wid] = sq;
    }
    __syncthreads();
    if (tid == 0){
        float S20 = 0.0f, S21 = 0.0f;
#pragma unroll
        for (int i = 0; i < 8; i++){ S20 += s_red[i]; S21 += s_red[8 + i]; }
        atomicAdd(&g_cos_sum, 0.5f * ((S20 - s_scal[0]) + (S21 - s_scal[2])));
        atomicAdd(&g_acc_cnt, s_scal[1] + s_scal[3]);
    }
}

// ---------------- K4: finalize -------------------------------------------
__global__ void k_final(float* __restrict__ out){
    if (threadIdx.x == 0){
        out[0] = g_cos_sum / (float)NPAIRS;
        out[1] = g_acc_cnt / (float)CQ;
    }
}

// ---------------- launch ---------------------------------------------------
extern "C" void kernel_launch(void* const* d_in, const int* in_sizes, int n_in,
                              void* d_out, int out_size){
    const float* xs = (const float*)d_in[0];
    const float* xq = (const float*)d_in[1];
    const float* W  = (const float*)d_in[2];
    float* out = (float*)d_out;
    (void)in_sizes; (void)n_in; (void)out_size;

    const int smem_gemm = 2 * G_BUF * (int)sizeof(float);       // 66 KB
    const int smem_dloo = 128 * 264 * (int)sizeof(float);       // 135 KB (>= 2*D_BUF)
    cudaFuncSetAttribute(k_gemm, cudaFuncAttributeMaxDynamicSharedMemorySize, smem_gemm);
    cudaFuncSetAttribute(k_dloo, cudaFuncAttributeMaxDynamicSharedMemorySize, smem_dloo);

    k_wsplit<<<32, 256>>>(W);
    k_gemm<<<M_TOT / 128, 512, smem_gemm>>>(xs, xq);
    k_proto<<<C_CLS, 128>>>();
    k_dloo<<<128, 512, smem_dloo>>>();
    k_final<<<1, 1>>>(out);
}

// round 11
// speedup vs baseline: 1.5499x; 1.5499x over previous
#include <cuda_runtime.h>
#include <cuda_fp16.h>
#include <cstdint>

// Problem constants (fixed by reference setup_inputs)
#define C_CLS 256
#define S_SUP 5
#define Q_QRY 64
#define DIN   1024
#define ZD    128
#define CS    (C_CLS*S_SUP)              // 1280
#define CQ    (C_CLS*Q_QRY)              // 16384
#define M_TOT (CS+CQ)                    // 17664
#define NPAIRS (C_CLS*(Q_QRY*(Q_QRY-1)/2)) // 516096
#define EPSF  1e-8f
#define NSTG  64                          // k_gemm: K stages of 16
#define DLSTG 8                           // k_dloo: K stages of 16

// k_gemm smem geometry (halves): Ah|Al|Bh|Bl, 2048 halves each
#define G_AL  2048
#define G_BH  4096
#define G_BL  6144
#define G_BUF 8192                        // per-buffer halves (16 KB)
// k_dloo smem geometry (halves): Ah|Al (2048 each) | Bh|Bl (4096 each)
#define D_AL  2048
#define D_BH  4096
#define D_BL  8192
#define D_BUF 12288                       // per-buffer halves (24 KB)

// ---------------- device scratch (no allocations allowed) ----------------
__device__ __align__(16) float g_z[(size_t)M_TOT * ZD];        // ~9 MB
__device__ __align__(16) float g_proto2[C_CLS];                // ||proto_c||^2
__device__ __align__(16) float g_row2[M_TOT];                  // ||z_row||^2
// 32*W fp16 hi/lo images: [k16(64)][n(128)][16 pos]  pos=[2t,2t+1,2t+8,2t+9]
__device__ __align__(16) __half g_Wh[64 * 2048];               // 256 KB
__device__ __align__(16) __half g_Wl[64 * 2048];               // 256 KB
// protoT fp16 hi/lo images: [k16(8)][n(256)][16 pos]
__device__ __align__(16) __half g_Ph[8 * 4096];                // 64 KB
__device__ __align__(16) __half g_Pl[8 * 4096];                // 64 KB
__device__ float g_cos_sum;
__device__ float g_acc_cnt;

// ---------------- helpers ----------------
__device__ __forceinline__ uint32_t smem_u32(const void* p){
    uint32_t a; asm("{ .reg .u64 t; cvta.to.shared.u64 t, %1; cvt.u32.u64 %0, t; }"
                    : "=r"(a) : "l"(p));
    return a;
}
__device__ __forceinline__ void cp16(uint32_t saddr, const void* g){
    asm volatile("cp.async.cg.shared.global [%0], [%1], 16;" :: "r"(saddr), "l"(g));
}
#define CP_COMMIT() asm volatile("cp.async.commit_group;" ::: "memory")
#define CP_WAIT0()  asm volatile("cp.async.wait_group 0;"  ::: "memory")

// D += A(16x16,row) * B(16x8,col)  fp16 inputs, fp32 accumulate
__device__ __forceinline__ void mma16(float4 &d, uint32_t a0, uint32_t a1,
                                      uint32_t a2, uint32_t a3,
                                      uint32_t b0, uint32_t b1){
    asm volatile("mma.sync.aligned.m16n8k16.row.col.f32.f16.f16.f32 "
        "{%0,%1,%2,%3}, {%4,%5,%6,%7}, {%8,%9}, {%0,%1,%2,%3};"
        : "+f"(d.x), "+f"(d.y), "+f"(d.z), "+f"(d.w)
        : "r"(a0), "r"(a1), "r"(a2), "r"(a3), "r"(b0), "r"(b1));
}
// split float2 -> fp16 hi (packed) + exact residual lo (packed)
__device__ __forceinline__ void hsplit2(float2 v, uint32_t &hi, uint32_t &lo){
    __half2 h = __float22half2_rn(v);
    float2 hf = __half22float2(h);
    __half2 l = __float22half2_rn(make_float2(v.x - hf.x, v.y - hf.y));
    hi = *(uint32_t*)&h;
    lo = *(uint32_t*)&l;
}

// =====================================================================
// KW: split 32*W[k=1024][n=128] into fp16 hi/lo images.
// Layout [k16 s][n][pos], pos block t (4 halves) = k {2t,2t+1,2t+8,2t+9}.
// =====================================================================
__global__ __launch_bounds__(256) void k_wsplit(const float* __restrict__ W){
    const int s = blockIdx.x;            // 0..63
    const int n = threadIdx.x >> 1;
    const int h = threadIdx.x & 1;
#pragma unroll
    for (int dt = 0; dt < 2; dt++){
        const int t  = 2 * h + dt;
        const int kb = s * 16 + 2 * t;
        const float2 vab = make_float2(32.f * W[(size_t)(kb + 0) * ZD + n],
                                       32.f * W[(size_t)(kb + 1) * ZD + n]);
        const float2 vcd = make_float2(32.f * W[(size_t)(kb + 8) * ZD + n],
                                       32.f * W[(size_t)(kb + 9) * ZD + n]);
        uint32_t h01, l01, h89, l89;
        hsplit2(vab, h01, l01);
        hsplit2(vcd, h89, l89);
        const int off = s * 2048 + n * 16 + t * 4;
        *(uint2*)&g_Wh[off] = make_uint2(h01, h89);
        *(uint2*)&g_Wl[off] = make_uint2(l01, l89);
    }
}

// =====================================================================
// K1: z = [xs; xq] @ W via fp16 double-double mma (m16n8k16, 3 passes,
// single accumulator). 512 threads = 16 warps (4m x 4n), warp tile
// 32x32, K=16/stage, 64 stages double-buffered (32 KB). B via cp.async
// from prebuilt hi/lo images; A split at staging. Epilogue: z = acc/32
// + fused ||row||^2.
// =====================================================================
__global__ __launch_bounds__(512) void k_gemm(const float* __restrict__ xs,
                                              const float* __restrict__ xq){
    extern __shared__ __half sh[];       // 2 x G_BUF halves (32 KB)
    __shared__ float s_r2[128];

    const int tid  = threadIdx.x;
    const int lane = tid & 31;
    const int wid  = tid >> 5;
    const int g    = lane >> 2;
    const int tg   = lane & 3;
    const int m0   = (wid & 3) * 32;
    const int n0   = (wid >> 2) * 32;
    const int bm   = blockIdx.x;
    const float* X = (bm < 10) ? (xs + (size_t)bm * (128 * DIN))
                               : (xq + (size_t)(bm - 10) * (128 * DIN));
    const int sm_m = tid >> 2;           // staging row 0..127
    const int st   = tid & 3;            // staging pos-block
    const int sts_off = sm_m * 16 + st * 4;

    float4 acc[2][4];
#pragma unroll
    for (int i = 0; i < 2; i++)
#pragma unroll
        for (int j = 0; j < 4; j++) acc[i][j] = make_float4(0.f, 0.f, 0.f, 0.f);

    float2 rA0, rA1;
    // prologue: stage 0
    {
        __half* buf = sh;
        if (tid < 256) cp16(smem_u32(&buf[G_BH]) + tid * 16, g_Wh + tid * 8);
        else           cp16(smem_u32(&buf[G_BL]) + (tid - 256) * 16, g_Wl + (tid - 256) * 8);
        CP_COMMIT();
        const float* xp = X + (size_t)sm_m * DIN + 2 * st;
        rA0 = *(const float2*)xp;
        rA1 = *(const float2*)(xp + 8);
        uint32_t h01, l01, h89, l89;
        hsplit2(rA0, h01, l01);
        hsplit2(rA1, h89, l89);
        *(uint2*)&buf[sts_off]        = make_uint2(h01, h89);
        *(uint2*)&buf[G_AL + sts_off] = make_uint2(l01, l89);
        CP_WAIT0();
    }
    __syncthreads();

    for (int s = 0; s < NSTG; s++){
        const int b = s & 1;
        const __half* buf = sh + b * G_BUF;
        __half* nbuf = sh + (b ^ 1) * G_BUF;
        if (s + 1 < NSTG){
            const __half* src = (tid < 256) ? (g_Wh + (s + 1) * 2048 + tid * 8)
                                            : (g_Wl + (s + 1) * 2048 + (tid - 256) * 8);
            const uint32_t dst = (tid < 256) ? (smem_u32(&nbuf[G_BH]) + tid * 16)
                                             : (smem_u32(&nbuf[G_BL]) + (tid - 256) * 16);
            cp16(dst, src);
            CP_COMMIT();
            const float* xp = X + (size_t)sm_m * DIN + (s + 1) * 16 + 2 * st;
            rA0 = *(const float2*)xp;
            rA1 = *(const float2*)(xp + 8);
        }
        // A fragments (one LDS.64 per row-half per hi/lo)
        uint2 AH[2][2], AL[2][2];
#pragma unroll
        for (int mt = 0; mt < 2; mt++){
            const int r0 = (m0 + mt * 16 + g) * 16 + tg * 4;
            AH[mt][0] = *(const uint2*)&buf[r0];
            AH[mt][1] = *(const uint2*)&buf[r0 + 128];          // row +8
            AL[mt][0] = *(const uint2*)&buf[G_AL + r0];
            AL[mt][1] = *(const uint2*)&buf[G_AL + r0 + 128];
        }
#pragma unroll
        for (int j = 0; j < 4; j++){
            const int nb = (n0 + j * 8 + g) * 16 + tg * 4;
            const uint2 bh = *(const uint2*)&buf[G_BH + nb];
            const uint2 bl = *(const uint2*)&buf[G_BL + nb];
#pragma unroll
            for (int mt = 0; mt < 2; mt++){
                mma16(acc[mt][j], AH[mt][0].x, AH[mt][1].x, AH[mt][0].y, AH[mt][1].y, bh.x, bh.y);
                mma16(acc[mt][j], AL[mt][0].x, AL[mt][1].x, AL[mt][0].y, AL[mt][1].y, bh.x, bh.y);
                mma16(acc[mt][j], AH[mt][0].x, AH[mt][1].x, AH[mt][0].y, AH[mt][1].y, bl.x, bl.y);
            }
        }
        if (s + 1 < NSTG){
            uint32_t h01, l01, h89, l89;
            hsplit2(rA0, h01, l01);
            hsplit2(rA1, h89, l89);
            *(uint2*)&nbuf[sts_off]        = make_uint2(h01, h89);
            *(uint2*)&nbuf[G_AL + sts_off] = make_uint2(l01, l89);
            CP_WAIT0();
            __syncthreads();
        }
    }

    // ---- epilogue: z = acc/32, store + fused row norms ----
    if (tid < 128) s_r2[tid] = 0.0f;
    __syncthreads();
    const size_t rb = (size_t)bm * 128;
    const float inv32 = 1.0f / 32.0f;
#pragma unroll
    for (int mt = 0; mt < 2; mt++){
        const int r0 = m0 + mt * 16 + g;
        float s0 = 0.0f, s1 = 0.0f;
#pragma unroll
        for (int j = 0; j < 4; j++){
            float4 a = acc[mt][j];
            a.x *= inv32; a.y *= inv32; a.z *= inv32; a.w *= inv32;
            const int col = n0 + j * 8 + 2 * tg;
            *(float2*)(g_z + (rb + r0) * ZD + col)     = make_float2(a.x, a.y);
            *(float2*)(g_z + (rb + r0 + 8) * ZD + col) = make_float2(a.z, a.w);
            s0 = fmaf(a.x, a.x, s0); s0 = fmaf(a.y, a.y, s0);
            s1 = fmaf(a.z, a.z, s1); s1 = fmaf(a.w, a.w, s1);
        }
        s0 += __shfl_xor_sync(0xffffffffu, s0, 1);
        s0 += __shfl_xor_sync(0xffffffffu, s0, 2);
        s1 += __shfl_xor_sync(0xffffffffu, s1, 1);
        s1 += __shfl_xor_sync(0xffffffffu, s1, 2);
        if (tg == 0){
            atomicAdd(&s_r2[r0],     s0);
            atomicAdd(&s_r2[r0 + 8], s1);
        }
    }
    __syncthreads();
    if (tid < 128) g_row2[rb + tid] = s_r2[tid];
}

// ---------------- K2: prototypes + ||proto||^2 + fp16 hi/lo images ------
// Image [k16(8)][n(256)][16 pos]; pos for kk=d&15:
// pos = ((kk>>1)&3)*4 + ((kk>>3)&1)*2 + (kk&1). Zeroes accumulators.
__global__ __launch_bounds__(128) void k_proto(){
    const int c = blockIdx.x;
    const int d = threadIdx.x;  // 0..127 (= k index)
    if (c == 0 && d == 0){ g_cos_sum = 0.0f; g_acc_cnt = 0.0f; }
    const float* z = g_z + (size_t)c * S_SUP * ZD + d;
    float p = 0.0f;
#pragma unroll
    for (int s = 0; s < S_SUP; s++) p += z[s * ZD];
    p *= (1.0f / S_SUP);
    const int k16 = d >> 4;
    const int kk  = d & 15;
    const int pos = ((kk >> 1) & 3) * 4 + ((kk >> 3) & 1) * 2 + (kk & 1);
    const __half hi = __float2half_rn(p);
    const int off = k16 * 4096 + c * 16 + pos;
    g_Ph[off] = hi;
    g_Pl[off] = __float2half_rn(p - __half2float(hi));
    float sq = p * p;
#pragma unroll
    for (int o = 16; o; o >>= 1) sq += __shfl_xor_sync(0xffffffffu, sq, o);
    __shared__ float w[4];
    if ((d & 31) == 0) w[d >> 5] = sq;
    __syncthreads();
    if (d == 0) g_proto2[c] = w[0] + w[1] + w[2] + w[3];
}

// =====================================================================
// K3 (fused d2 + loo): one CTA per 2 classes. GEMM M=128 x N=256 x K=128,
// fp16 double-double 3-pass, warp tile 32x64 (16 warps: 4m x 4n).
// d2 -> SMEM (stride 264), then in-CTA loo-norm + cos identity + argmin.
// cos: sum_{q<k} a_q.a_k = ( ||sum_q a_q||^2 - sum_q ||a_q||^2 ) / 2
// =====================================================================
__global__ __launch_bounds__(512) void k_dloo(){
    extern __shared__ __half sh[];       // buffers; d2s aliases as float*
    __shared__ float s_part[16][256];
    __shared__ float s_red[16];
    __shared__ float s_scal[4];          // [sumA2_c0, cnt_c0, sumA2_c1, cnt_c1]

    const int tid  = threadIdx.x;
    const int lane = tid & 31;
    const int wid  = tid >> 5;           // 0..15
    const int g    = lane >> 2;
    const int tg   = lane & 3;
    const int m0   = (wid & 3) * 32;
    const int n0   = (wid >> 2) * 64;
    const int qb   = blockIdx.x;         // class pair
    const float* X = g_z + (size_t)(CS + qb * 128) * ZD;
    const int sm_m = tid >> 2;
    const int st   = tid & 3;
    const int sts_off = sm_m * 16 + st * 4;

    if (tid < 4) s_scal[tid] = 0.0f;

    float4 acc[2][8];
#pragma unroll
    for (int i = 0; i < 2; i++)
#pragma unroll
        for (int j = 0; j < 8; j++) acc[i][j] = make_float4(0.f, 0.f, 0.f, 0.f);

    float2 rA0, rA1;
    // prologue: stage 0
    {
        __half* buf = sh;
        cp16(smem_u32(&buf[D_BH]) + tid * 16, g_Ph + tid * 8);
        cp16(smem_u32(&buf[D_BL]) + tid * 16, g_Pl + tid * 8);
        CP_COMMIT();
        const float* xp = X + (size_t)sm_m * ZD + 2 * st;
        rA0 = *(const float2*)xp;
        rA1 = *(const float2*)(xp + 8);
        uint32_t h01, l01, h89, l89;
        hsplit2(rA0, h01, l01);
        hsplit2(rA1, h89, l89);
        *(uint2*)&buf[sts_off]        = make_uint2(h01, h89);
        *(uint2*)&buf[D_AL + sts_off] = make_uint2(l01, l89);
        CP_WAIT0();
    }
    __syncthreads();

    for (int s = 0; s < DLSTG; s++){
        const int b = s & 1;
        const __half* buf = sh + b * D_BUF;
        __half* nbuf = sh + (b ^ 1) * D_BUF;
        if (s + 1 < DLSTG){
            cp16(smem_u32(&nbuf[D_BH]) + tid * 16, g_Ph + (s + 1) * 4096 + tid * 8);
            cp16(smem_u32(&nbuf[D_BL]) + tid * 16, g_Pl + (s + 1) * 4096 + tid * 8);
            CP_COMMIT();
            const float* xp = X + (size_t)sm_m * ZD + (s + 1) * 16 + 2 * st;
            rA0 = *(const float2*)xp;
            rA1 = *(const float2*)(xp + 8);
        }
        uint2 AH[2][2], AL[2][2];
#pragma unroll
        for (int mt = 0; mt < 2; mt++){
            const int r0 = (m0 + mt * 16 + g) * 16 + tg * 4;
            AH[mt][0] = *(const uint2*)&buf[r0];
            AH[mt][1] = *(const uint2*)&buf[r0 + 128];
            AL[mt][0] = *(const uint2*)&buf[D_AL + r0];
            AL[mt][1] = *(const uint2*)&buf[D_AL + r0 + 128];
        }
#pragma unroll
        for (int j = 0; j < 8; j++){
            const int nb = (n0 + j * 8 + g) * 16 + tg * 4;
            const uint2 bh = *(const uint2*)&buf[D_BH + nb];
            const uint2 bl = *(const uint2*)&buf[D_BL + nb];
#pragma unroll
            for (int mt = 0; mt < 2; mt++){
                mma16(acc[mt][j], AH[mt][0].x, AH[mt][1].x, AH[mt][0].y, AH[mt][1].y, bh.x, bh.y);
                mma16(acc[mt][j], AL[mt][0].x, AL[mt][1].x, AL[mt][0].y, AL[mt][1].y, bh.x, bh.y);
                mma16(acc[mt][j], AH[mt][0].x, AH[mt][1].x, AH[mt][0].y, AH[mt][1].y, bl.x, bl.y);
            }
        }
        if (s + 1 < DLSTG){
            uint32_t h01, l01, h89, l89;
            hsplit2(rA0, h01, l01);
            hsplit2(rA1, h89, l89);
            *(uint2*)&nbuf[sts_off]        = make_uint2(h01, h89);
            *(uint2*)&nbuf[D_AL + sts_off] = make_uint2(l01, l89);
            CP_WAIT0();
            __syncthreads();
        }
    }

    // ---- d2 into SMEM (reuses stage buffers; stride 264 floats) ----
    __syncthreads();                     // all warps done reading buffers
    float* d2s = (float*)sh;             // 128 x 264 floats
#pragma unroll
    for (int mt = 0; mt < 2; mt++){
        const int r = m0 + mt * 16 + g;
        const float qn0 = g_row2[CS + qb * 128 + r];
        const float qn1 = g_row2[CS + qb * 128 + r + 8];
#pragma unroll
        for (int j = 0; j < 8; j++){
            const int col = n0 + j * 8 + 2 * tg;
            const float pn0 = g_proto2[col];
            const float pn1 = g_proto2[col + 1];
            const float4 a = acc[mt][j];
            *(float2*)&d2s[r * 264 + col] =
                make_float2(qn0 + pn0 - 2.0f * a.x, qn0 + pn1 - 2.0f * a.y);
            *(float2*)&d2s[(r + 8) * 264 + col] =
                make_float2(qn1 + pn0 - 2.0f * a.z, qn1 + pn1 - 2.0f * a.w);
        }
    }
    __syncthreads();

    // ---- loo: warp w -> rows w*8..w*8+7; class = 2qb + (w>>3) ----
    const int cls = 2 * qb + (wid >> 3);
    const float* D = d2s + (size_t)(wid * 8) * 264 + lane * 8;
    float d2v[8][8];
#pragma unroll
    for (int r = 0; r < 8; r++){
        const float4 v0 = *(const float4*)(D + r * 264);
        const float4 v1 = *(const float4*)(D + r * 264 + 4);
        d2v[r][0] = v0.x; d2v[r][1] = v0.y; d2v[r][2] = v0.z; d2v[r][3] = v0.w;
        d2v[r][4] = v1.x; d2v[r][5] = v1.y; d2v[r][6] = v1.z; d2v[r][7] = v1.w;
    }

    float sacc[8];
#pragma unroll
    for (int j = 0; j < 8; j++) sacc[j] = 0.0f;
    float sumA2 = 0.0f;
    float cnt   = 0.0f;

#pragma unroll
    for (int r = 0; r < 8; r++){
        float ss = 0.0f;
        float mv = 3.4e38f;
        int   mi = 1 << 30;
#pragma unroll
        for (int j = 0; j < 8; j++){
            const int   p = lane * 8 + j;
            const float v = d2v[r][j];
            if (v < mv){ mv = v; mi = p; }        // ascending -> first min
            if (p != cls) ss = fmaf(v, v, ss);
        }
#pragma unroll
        for (int off = 16; off; off >>= 1){
            ss += __shfl_xor_sync(0xffffffffu, ss, off);
            const float ov = __shfl_xor_sync(0xffffffffu, mv, off);
            const int   oi = __shfl_xor_sync(0xffffffffu, mi, off);
            if (ov < mv || (ov == mv && oi < mi)){ mv = ov; mi = oi; }
        }
        const float inv = 1.0f / fmaxf(sqrtf(ss), EPSF);
#pragma unroll
        for (int j = 0; j < 8; j++){
            const int p = lane * 8 + j;
            if (p != cls) sacc[j] = fmaf(d2v[r][j], inv, sacc[j]);
        }
        if (lane == 0){
            sumA2 += ss * inv * inv;
            if (mi == cls) cnt += 1.0f;
        }
    }

#pragma unroll
    for (int j = 0; j < 8; j++) s_part[wid][lane * 8 + j] = sacc[j];
    if (lane == 0){
        atomicAdd(&s_scal[(wid >> 3) * 2],     sumA2);
        atomicAdd(&s_scal[(wid >> 3) * 2 + 1], cnt);
    }
    __syncthreads();

    // ||sum_q a_q||^2 per class: threads 0-255 -> class0, 256-511 -> class1
    {
        const int half = tid >> 8;
        const int cc   = tid & 255;
        float col = 0.0f;
#pragma unroll
        for (int w2 = 0; w2 < 8; w2++) col += s_part[half * 8 + w2][cc];
        float sq = col * col;
#pragma unroll
        for (int off = 16; off; off >>= 1) sq += __shfl_xor_sync(0xffffffffu, sq, off);
        if (lane == 0) s_red[wid] = sq;
    }
    __syncthreads();
    if (tid == 0){
        float S20 = 0.0f, S21 = 0.0f;
#pragma unroll
        for (int i = 0; i < 8; i++){ S20 += s_red[i]; S21 += s_red[8 + i]; }
        atomicAdd(&g_cos_sum, 0.5f * ((S20 - s_scal[0]) + (S21 - s_scal[2])));
        atomicAdd(&g_acc_cnt, s_scal[1] + s_scal[3]);
    }
}

// ---------------- K4: finalize -------------------------------------------
__global__ void k_final(float* __restrict__ out){
    if (threadIdx.x == 0){
        out[0] = g_cos_sum / (float)NPAIRS;
        out[1] = g_acc_cnt / (float)CQ;
    }
}

// ---------------- launch ---------------------------------------------------
extern "C" void kernel_launch(void* const* d_in, const int* in_sizes, int n_in,
                              void* d_out, int out_size){
    const float* xs = (const float*)d_in[0];
    const float* xq = (const float*)d_in[1];
    const float* W  = (const float*)d_in[2];
    float* out = (float*)d_out;
    (void)in_sizes; (void)n_in; (void)out_size;

    const int smem_gemm = 2 * G_BUF * (int)sizeof(__half);      // 32 KB
    const int smem_dloo = 128 * 264 * (int)sizeof(float);       // 135 KB (>= 2*D_BUF*2B)
    cudaFuncSetAttribute(k_gemm, cudaFuncAttributeMaxDynamicSharedMemorySize, smem_gemm);
    cudaFuncSetAttribute(k_dloo, cudaFuncAttributeMaxDynamicSharedMemorySize, smem_dloo);

    k_wsplit<<<64, 256>>>(W);
    k_gemm<<<M_TOT / 128, 512, smem_gemm>>>(xs, xq);
    k_proto<<<C_CLS, 128>>>();
    k_dloo<<<128, 512, smem_dloo>>>();
    k_final<<<1, 1>>>(out);
}